// round 5
// baseline (speedup 1.0000x reference)
#include <cuda_runtime.h>

#define N_ROWS 65536
#define D      64
#define NE     1024
#define CHUNK  128
#define K2_THREADS 128
#define K2_BLOCKS  (N_ROWS / K2_THREADS)   // 512
#define GAP_THRESH 1e-4f
#define REFINE_BLOCKS 256
#define REFINE_THREADS 128

// Scratch (no allocations allowed)
__device__ float g_e2[NE];
__device__ float g_partial[K2_BLOCKS];
__device__ int   g_flag_cnt;
__device__ int   g_flag_rows[N_ROWS];

// ---------------------------------------------------------------------------
// Packed f32x2 helpers (sm_103a): one instruction = two IEEE fp32 FMAs.
// Operands come straight from ulonglong2 (LDS.128 -> two aligned f32 pairs),
// so NO packing MOVs are needed in the hot loop.
// ---------------------------------------------------------------------------
__device__ __forceinline__ unsigned long long fma_f32x2(
    unsigned long long a, unsigned long long b, unsigned long long c) {
    unsigned long long d;
    asm("fma.rn.f32x2 %0, %1, %2, %3;" : "=l"(d) : "l"(a), "l"(b), "l"(c));
    return d;
}
__device__ __forceinline__ void unpack_f2(unsigned long long v, float& lo, float& hi) {
    asm("mov.b64 {%0, %1}, %2;" : "=f"(lo), "=f"(hi) : "l"(v));
}
__device__ __forceinline__ float hsum_f2(unsigned long long v) {
    float lo, hi;
    unpack_f2(v, lo, hi);
    return lo + hi;
}

// ---------------------------------------------------------------------------
// Kernel 1: e2[j] = sum_d emb[j,d]^2   (+ reset flag counter)
// ---------------------------------------------------------------------------
__global__ void e2_kernel(const float* __restrict__ emb) {
    int j = blockIdx.x * blockDim.x + threadIdx.x;
    if (j == 0) g_flag_cnt = 0;
    if (j < NE) {
        const float4* e = (const float4*)(emb + (size_t)j * D);
        float s = 0.f;
        #pragma unroll
        for (int q = 0; q < 16; q++) {
            float4 v = e[q];
            s += v.x * v.x;
            s += v.y * v.y;
            s += v.z * v.z;
            s += v.w * v.w;
        }
        g_e2[j] = s;
    }
}

// ---------------------------------------------------------------------------
// Kernel 2: fused argmin + zq gather + loss partial.
// 1 row/thread; codes streamed through shared (as ulonglong2 -> direct f32x2
// operands); 4-code register blocking: 64 LDS.128 + 128 FFMA2 per group.
// Epilogue: writes idx, writes straight-through zq from emb[besti] (L2-hot),
// loss partial taken from bestd (same value, ~1e-7 rel rounding difference).
// Near-ties (gap < GAP_THRESH) -> refine list; refine patches idx+zq; no
// loss correction needed (|delta d| < 1e-4 vs sum ~4.2e6 -> <1e-8 rel).
// ---------------------------------------------------------------------------
__global__ __launch_bounds__(K2_THREADS)
void argmin_kernel(const float* __restrict__ z,
                   const float* __restrict__ emb,
                   float* __restrict__ zq_out,
                   float* __restrict__ idx_out_f) {
    __shared__ ulonglong2 sE[CHUNK * 16];
    __shared__ float      sE2[CHUNK];
    __shared__ float      red[K2_THREADS];

    int row = blockIdx.x * K2_THREADS + threadIdx.x;

    // z row: 32 packed dim-pairs (loaded as ulonglong2, already pair-aligned)
    unsigned long long zu[32];
    {
        const ulonglong2* zp = (const ulonglong2*)(z + (size_t)row * D);
        #pragma unroll
        for (int q = 0; q < 16; q++) {
            ulonglong2 v = zp[q];
            zu[2 * q + 0] = v.x;
            zu[2 * q + 1] = v.y;
        }
    }
    // z2 in the same sequential order as before (matches passing round)
    float z2 = 0.f;
    #pragma unroll
    for (int q = 0; q < 32; q++) {
        float a, b;
        unpack_f2(zu[q], a, b);
        z2 += a * a;
        z2 += b * b;
    }

    float bestd  = 3.402823466e38f;
    float best2d = 3.402823466e38f;
    int   besti  = 0;

    const ulonglong2* ef = (const ulonglong2*)emb;

    for (int c0 = 0; c0 < NE; c0 += CHUNK) {
        __syncthreads();
        for (int t = threadIdx.x; t < CHUNK * 16; t += K2_THREADS)
            sE[t] = ef[c0 * 16 + t];
        sE2[threadIdx.x] = g_e2[c0 + threadIdx.x];   // K2_THREADS == CHUNK
        __syncthreads();

        #pragma unroll 1
        for (int j = 0; j < CHUNK; j += 4) {
            unsigned long long a0 = 0ull, a1 = 0ull, a2 = 0ull, a3 = 0ull;
            #pragma unroll
            for (int q = 0; q < 16; q++) {
                ulonglong2 b0 = sE[(j + 0) * 16 + q];
                ulonglong2 b1 = sE[(j + 1) * 16 + q];
                ulonglong2 b2 = sE[(j + 2) * 16 + q];
                ulonglong2 b3 = sE[(j + 3) * 16 + q];
                unsigned long long ze = zu[2 * q + 0];
                unsigned long long zo = zu[2 * q + 1];
                a0 = fma_f32x2(ze, b0.x, a0);
                a0 = fma_f32x2(zo, b0.y, a0);
                a1 = fma_f32x2(ze, b1.x, a1);
                a1 = fma_f32x2(zo, b1.y, a1);
                a2 = fma_f32x2(ze, b2.x, a2);
                a2 = fma_f32x2(zo, b2.y, a2);
                a3 = fma_f32x2(ze, b3.x, a3);
                a3 = fma_f32x2(zo, b3.y, a3);
            }
            float dd0 = (z2 + sE2[j + 0]) - 2.f * hsum_f2(a0);
            float dd1 = (z2 + sE2[j + 1]) - 2.f * hsum_f2(a1);
            float dd2 = (z2 + sE2[j + 2]) - 2.f * hsum_f2(a2);
            float dd3 = (z2 + sE2[j + 3]) - 2.f * hsum_f2(a3);
            if (dd0 < bestd) { best2d = bestd; bestd = dd0; besti = c0 + j + 0; }
            else if (dd0 < best2d) best2d = dd0;
            if (dd1 < bestd) { best2d = bestd; bestd = dd1; besti = c0 + j + 1; }
            else if (dd1 < best2d) best2d = dd1;
            if (dd2 < bestd) { best2d = bestd; bestd = dd2; besti = c0 + j + 2; }
            else if (dd2 < best2d) best2d = dd2;
            if (dd3 < bestd) { best2d = bestd; bestd = dd3; besti = c0 + j + 3; }
            else if (dd3 < best2d) best2d = dd3;
        }
    }

    // ---- epilogue: idx, zq (straight-through), flag, loss partial ----
    idx_out_f[row] = (float)besti;

    {
        const float4* eq = (const float4*)(emb + (size_t)besti * D);
        float4 ev[16];
        #pragma unroll
        for (int q = 0; q < 16; q++) ev[q] = eq[q];   // batched LDG.128, L2-hot

        float* o = zq_out + (size_t)row * D;          // 4B-aligned only
        #pragma unroll
        for (int q = 0; q < 16; q++) {
            float f0, f1, f2, f3;
            unpack_f2(zu[2 * q + 0], f0, f1);
            unpack_f2(zu[2 * q + 1], f2, f3);
            o[q * 4 + 0] = __fadd_rn(f0, __fadd_rn(ev[q].x, -f0));
            o[q * 4 + 1] = __fadd_rn(f1, __fadd_rn(ev[q].y, -f1));
            o[q * 4 + 2] = __fadd_rn(f2, __fadd_rn(ev[q].z, -f2));
            o[q * 4 + 3] = __fadd_rn(f3, __fadd_rn(ev[q].w, -f3));
        }
    }

    if (best2d - bestd < GAP_THRESH) {
        int slot = atomicAdd(&g_flag_cnt, 1);
        g_flag_rows[slot] = row;
    }

    red[threadIdx.x] = bestd;
    __syncthreads();
    #pragma unroll
    for (int st = K2_THREADS / 2; st > 0; st >>= 1) {
        if (threadIdx.x < st) red[threadIdx.x] += red[threadIdx.x + st];
        __syncthreads();
    }
    if (threadIdx.x == 0) g_partial[blockIdx.x] = red[0];
}

// ---------------------------------------------------------------------------
// Kernel 2b: refine flagged rows with Kahan-compensated dots; rewrite idx
// and zq for those rows. (Loss stays from the main pass: the d-difference
// for any flip is < GAP_THRESH -> <1e-8 relative on the loss.)
// ---------------------------------------------------------------------------
__global__ __launch_bounds__(REFINE_THREADS)
void refine_kernel(const float* __restrict__ z,
                   const float* __restrict__ emb,
                   float* __restrict__ zq_out,
                   float* __restrict__ idx_out_f) {
    __shared__ float sz[D];
    __shared__ float sd[REFINE_THREADS];
    __shared__ int   si[REFINE_THREADS];

    int cnt = g_flag_cnt;
    for (int w = blockIdx.x; w < cnt; w += gridDim.x) {
        int row = g_flag_rows[w];

        __syncthreads();
        if (threadIdx.x < D) sz[threadIdx.x] = z[(size_t)row * D + threadIdx.x];
        __syncthreads();

        float z2 = 0.f;
        #pragma unroll
        for (int k = 0; k < D; k++) z2 += sz[k] * sz[k];

        float bestd = 3.402823466e38f;
        int   besti = NE;

        for (int j = threadIdx.x; j < NE; j += REFINE_THREADS) {
            const float4* e = (const float4*)(emb + (size_t)j * D);
            float4 ev[16];
            #pragma unroll
            for (int q = 0; q < 16; q++) ev[q] = e[q];

            float s = 0.f, c = 0.f;
            #pragma unroll
            for (int q = 0; q < 16; q++) {
                float el[4] = {ev[q].x, ev[q].y, ev[q].z, ev[q].w};
                #pragma unroll
                for (int u = 0; u < 4; u++) {
                    float p = __fmul_rn(sz[q * 4 + u], el[u]);
                    float y = __fadd_rn(p, -c);
                    float t = __fadd_rn(s, y);
                    c = __fadd_rn(__fadd_rn(t, -s), -y);
                    s = t;
                }
            }
            float dot = __fadd_rn(s, c);
            float dd  = __fadd_rn(__fadd_rn(z2, g_e2[j]), -2.f * dot);
            if (dd < bestd || (dd == bestd && j < besti)) { bestd = dd; besti = j; }
        }

        sd[threadIdx.x] = bestd;
        si[threadIdx.x] = besti;
        __syncthreads();
        #pragma unroll
        for (int st = REFINE_THREADS / 2; st > 0; st >>= 1) {
            if (threadIdx.x < st) {
                float od = sd[threadIdx.x + st];
                int   oi = si[threadIdx.x + st];
                if (od < sd[threadIdx.x] ||
                    (od == sd[threadIdx.x] && oi < si[threadIdx.x])) {
                    sd[threadIdx.x] = od;
                    si[threadIdx.x] = oi;
                }
            }
            __syncthreads();
        }
        int win = si[0];
        __syncthreads();

        if (threadIdx.x == 0) idx_out_f[row] = (float)win;
        // rewrite zq row with the (possibly new) winner, straight-through form
        if (threadIdx.x < D) {
            float e  = emb[(size_t)win * D + threadIdx.x];
            float zv = sz[threadIdx.x];
            zq_out[(size_t)row * D + threadIdx.x] =
                __fadd_rn(zv, __fadd_rn(e, -zv));
        }
    }
}

// ---------------------------------------------------------------------------
// Kernel 3: final loss reduction over 512 partials.
// loss = 1.25 * sum / (N*D)
// ---------------------------------------------------------------------------
__global__ void final_kernel(float* __restrict__ out) {
    __shared__ float red[256];
    float s = g_partial[threadIdx.x] + g_partial[threadIdx.x + 256];
    red[threadIdx.x] = s;
    __syncthreads();
    #pragma unroll
    for (int st = 128; st > 0; st >>= 1) {
        if (threadIdx.x < st) red[threadIdx.x] += red[threadIdx.x + st];
        __syncthreads();
    }
    if (threadIdx.x == 0)
        out[0] = 1.25f * red[0] / (float)(N_ROWS * D);
}

// ---------------------------------------------------------------------------
// Launch: out layout = [loss(1) | z_q(N_ROWS*D) | indices(N_ROWS)] fp32
// ---------------------------------------------------------------------------
extern "C" void kernel_launch(void* const* d_in, const int* in_sizes, int n_in,
                              void* d_out, int out_size) {
    const float* z   = (const float*)d_in[0];
    const float* emb = (const float*)d_in[1];
    float* out     = (float*)d_out;
    float* zq_out  = out + 1;
    float* idx_out = out + 1 + (size_t)N_ROWS * D;

    e2_kernel<<<(NE + 255) / 256, 256>>>(emb);
    argmin_kernel<<<K2_BLOCKS, K2_THREADS>>>(z, emb, zq_out, idx_out);
    refine_kernel<<<REFINE_BLOCKS, REFINE_THREADS>>>(z, emb, zq_out, idx_out);
    final_kernel<<<1, 256>>>(out);
}

// round 6
// speedup vs baseline: 1.0958x; 1.0958x over previous
#include <cuda_runtime.h>

#define N_ROWS 65536
#define D      64
#define NE     1024
#define CHUNK  128
#define K2_THREADS 128
#define ROWS_PER_BLOCK (K2_THREADS * 2)
#define K2_BLOCKS  (N_ROWS / ROWS_PER_BLOCK)   // 256
#define GAP_THRESH 1e-4f
#define REFINE_BLOCKS 256
#define REFINE_THREADS 128
#define K3_THREADS 256
#define K3_BLOCKS  (N_ROWS * 4 / K3_THREADS)   // 4 threads/row -> 1024

// Scratch (no allocations allowed)
__device__ float g_e2[NE];
__device__ int   g_idx[N_ROWS];
__device__ float g_partial[K2_BLOCKS];
__device__ int   g_flag_cnt;
__device__ int   g_flag_rows[N_ROWS];

// ---------------------------------------------------------------------------
// Packed f32x2 helpers (sm_103a): one instruction = two IEEE fp32 FMAs.
// Operands come straight from ulonglong2 (LDS.128 -> two aligned f32 pairs).
// ---------------------------------------------------------------------------
__device__ __forceinline__ unsigned long long fma_f32x2(
    unsigned long long a, unsigned long long b, unsigned long long c) {
    unsigned long long d;
    asm("fma.rn.f32x2 %0, %1, %2, %3;" : "=l"(d) : "l"(a), "l"(b), "l"(c));
    return d;
}
__device__ __forceinline__ void unpack_f2(unsigned long long v, float& lo, float& hi) {
    asm("mov.b64 {%0, %1}, %2;" : "=f"(lo), "=f"(hi) : "l"(v));
}
__device__ __forceinline__ float hsum_f2(unsigned long long v) {
    float lo, hi;
    unpack_f2(v, lo, hi);
    return lo + hi;
}

// ---------------------------------------------------------------------------
// Kernel 1: e2[j] = sum_d emb[j,d]^2   (+ reset flag counter)
// ---------------------------------------------------------------------------
__global__ void e2_kernel(const float* __restrict__ emb) {
    int j = blockIdx.x * blockDim.x + threadIdx.x;
    if (j == 0) g_flag_cnt = 0;
    if (j < NE) {
        const float4* e = (const float4*)(emb + (size_t)j * D);
        float s = 0.f;
        #pragma unroll
        for (int q = 0; q < 16; q++) {
            float4 v = e[q];
            s += v.x * v.x;
            s += v.y * v.y;
            s += v.z * v.z;
            s += v.w * v.w;
        }
        g_e2[j] = s;
    }
}

// ---------------------------------------------------------------------------
// Kernel 2: argmin, 2 rows/thread x 4-code blocking.
// Each smem operand (ulonglong2) now feeds 4 FFMA2 (2 rows) -> LDS pressure
// halved vs round 5. Pure compute: writes g_idx, idx_out, flag list, and the
// per-block loss partial (sum of bestd). No zq epilogue (unfused; round-5
// fusion measured +34us).
// ---------------------------------------------------------------------------
__global__ __launch_bounds__(K2_THREADS)
void argmin_kernel(const float* __restrict__ z,
                   const float* __restrict__ emb,
                   float* __restrict__ idx_out_f) {
    __shared__ ulonglong2 sE[CHUNK * 16];     // 32 KB
    __shared__ float      sE2[CHUNK];
    __shared__ float      red[K2_THREADS];

    int row0 = blockIdx.x * ROWS_PER_BLOCK + threadIdx.x;
    int row1 = row0 + K2_THREADS;

    unsigned long long zu0[32], zu1[32];
    {
        const ulonglong2* zp0 = (const ulonglong2*)(z + (size_t)row0 * D);
        const ulonglong2* zp1 = (const ulonglong2*)(z + (size_t)row1 * D);
        #pragma unroll
        for (int q = 0; q < 16; q++) {
            ulonglong2 v0 = zp0[q];
            ulonglong2 v1 = zp1[q];
            zu0[2 * q + 0] = v0.x; zu0[2 * q + 1] = v0.y;
            zu1[2 * q + 0] = v1.x; zu1[2 * q + 1] = v1.y;
        }
    }
    float z20 = 0.f, z21 = 0.f;
    #pragma unroll
    for (int q = 0; q < 32; q++) {
        float a, b;
        unpack_f2(zu0[q], a, b); z20 += a * a; z20 += b * b;
        unpack_f2(zu1[q], a, b); z21 += a * a; z21 += b * b;
    }

    float bestd0  = 3.402823466e38f, best2d0 = 3.402823466e38f;
    float bestd1  = 3.402823466e38f, best2d1 = 3.402823466e38f;
    int   besti0  = 0, besti1 = 0;

    const ulonglong2* ef = (const ulonglong2*)emb;

    for (int c0 = 0; c0 < NE; c0 += CHUNK) {
        __syncthreads();
        for (int t = threadIdx.x; t < CHUNK * 16; t += K2_THREADS)
            sE[t] = ef[c0 * 16 + t];
        sE2[threadIdx.x] = g_e2[c0 + threadIdx.x];   // K2_THREADS == CHUNK
        __syncthreads();

        #pragma unroll 1
        for (int j = 0; j < CHUNK; j += 4) {
            unsigned long long a00 = 0ull, a01 = 0ull, a02 = 0ull, a03 = 0ull;
            unsigned long long a10 = 0ull, a11 = 0ull, a12 = 0ull, a13 = 0ull;
            #pragma unroll
            for (int q = 0; q < 16; q++) {
                ulonglong2 b0 = sE[(j + 0) * 16 + q];
                ulonglong2 b1 = sE[(j + 1) * 16 + q];
                ulonglong2 b2 = sE[(j + 2) * 16 + q];
                ulonglong2 b3 = sE[(j + 3) * 16 + q];
                unsigned long long z0e = zu0[2 * q + 0];
                unsigned long long z0o = zu0[2 * q + 1];
                unsigned long long z1e = zu1[2 * q + 0];
                unsigned long long z1o = zu1[2 * q + 1];
                a00 = fma_f32x2(z0e, b0.x, a00); a00 = fma_f32x2(z0o, b0.y, a00);
                a01 = fma_f32x2(z0e, b1.x, a01); a01 = fma_f32x2(z0o, b1.y, a01);
                a02 = fma_f32x2(z0e, b2.x, a02); a02 = fma_f32x2(z0o, b2.y, a02);
                a03 = fma_f32x2(z0e, b3.x, a03); a03 = fma_f32x2(z0o, b3.y, a03);
                a10 = fma_f32x2(z1e, b0.x, a10); a10 = fma_f32x2(z1o, b0.y, a10);
                a11 = fma_f32x2(z1e, b1.x, a11); a11 = fma_f32x2(z1o, b1.y, a11);
                a12 = fma_f32x2(z1e, b2.x, a12); a12 = fma_f32x2(z1o, b2.y, a12);
                a13 = fma_f32x2(z1e, b3.x, a13); a13 = fma_f32x2(z1o, b3.y, a13);
            }
            float e0 = sE2[j + 0], e1 = sE2[j + 1];
            float e2v = sE2[j + 2], e3 = sE2[j + 3];
            float d00 = (z20 + e0)  - 2.f * hsum_f2(a00);
            float d01 = (z20 + e1)  - 2.f * hsum_f2(a01);
            float d02 = (z20 + e2v) - 2.f * hsum_f2(a02);
            float d03 = (z20 + e3)  - 2.f * hsum_f2(a03);
            float d10 = (z21 + e0)  - 2.f * hsum_f2(a10);
            float d11 = (z21 + e1)  - 2.f * hsum_f2(a11);
            float d12 = (z21 + e2v) - 2.f * hsum_f2(a12);
            float d13 = (z21 + e3)  - 2.f * hsum_f2(a13);

            if (d00 < bestd0) { best2d0 = bestd0; bestd0 = d00; besti0 = c0 + j + 0; }
            else if (d00 < best2d0) best2d0 = d00;
            if (d01 < bestd0) { best2d0 = bestd0; bestd0 = d01; besti0 = c0 + j + 1; }
            else if (d01 < best2d0) best2d0 = d01;
            if (d02 < bestd0) { best2d0 = bestd0; bestd0 = d02; besti0 = c0 + j + 2; }
            else if (d02 < best2d0) best2d0 = d02;
            if (d03 < bestd0) { best2d0 = bestd0; bestd0 = d03; besti0 = c0 + j + 3; }
            else if (d03 < best2d0) best2d0 = d03;

            if (d10 < bestd1) { best2d1 = bestd1; bestd1 = d10; besti1 = c0 + j + 0; }
            else if (d10 < best2d1) best2d1 = d10;
            if (d11 < bestd1) { best2d1 = bestd1; bestd1 = d11; besti1 = c0 + j + 1; }
            else if (d11 < best2d1) best2d1 = d11;
            if (d12 < bestd1) { best2d1 = bestd1; bestd1 = d12; besti1 = c0 + j + 2; }
            else if (d12 < best2d1) best2d1 = d12;
            if (d13 < bestd1) { best2d1 = bestd1; bestd1 = d13; besti1 = c0 + j + 3; }
            else if (d13 < best2d1) best2d1 = d13;
        }
    }

    g_idx[row0]     = besti0;
    g_idx[row1]     = besti1;
    idx_out_f[row0] = (float)besti0;
    idx_out_f[row1] = (float)besti1;

    if (best2d0 - bestd0 < GAP_THRESH) {
        int slot = atomicAdd(&g_flag_cnt, 1);
        g_flag_rows[slot] = row0;
    }
    if (best2d1 - bestd1 < GAP_THRESH) {
        int slot = atomicAdd(&g_flag_cnt, 1);
        g_flag_rows[slot] = row1;
    }

    red[threadIdx.x] = bestd0 + bestd1;
    __syncthreads();
    #pragma unroll
    for (int st = K2_THREADS / 2; st > 0; st >>= 1) {
        if (threadIdx.x < st) red[threadIdx.x] += red[threadIdx.x + st];
        __syncthreads();
    }
    if (threadIdx.x == 0) g_partial[blockIdx.x] = red[0];
}

// ---------------------------------------------------------------------------
// Kernel 2b: refine flagged rows with Kahan-compensated dots; rewrite g_idx
// and idx_out only (gather runs after and re-reads g_idx). Loss stays from
// the main pass: any flip changes d by < GAP_THRESH -> <1e-8 rel on loss.
// ---------------------------------------------------------------------------
__global__ __launch_bounds__(REFINE_THREADS)
void refine_kernel(const float* __restrict__ z,
                   const float* __restrict__ emb,
                   float* __restrict__ idx_out_f) {
    __shared__ float sz[D];
    __shared__ float sd[REFINE_THREADS];
    __shared__ int   si[REFINE_THREADS];

    int cnt = g_flag_cnt;
    for (int w = blockIdx.x; w < cnt; w += gridDim.x) {
        int row = g_flag_rows[w];

        __syncthreads();
        if (threadIdx.x < D) sz[threadIdx.x] = z[(size_t)row * D + threadIdx.x];
        __syncthreads();

        float z2 = 0.f;
        #pragma unroll
        for (int k = 0; k < D; k++) z2 += sz[k] * sz[k];

        float bestd = 3.402823466e38f;
        int   besti = NE;

        for (int j = threadIdx.x; j < NE; j += REFINE_THREADS) {
            const float4* e = (const float4*)(emb + (size_t)j * D);
            float4 ev[16];
            #pragma unroll
            for (int q = 0; q < 16; q++) ev[q] = e[q];

            float s = 0.f, c = 0.f;
            #pragma unroll
            for (int q = 0; q < 16; q++) {
                float el[4] = {ev[q].x, ev[q].y, ev[q].z, ev[q].w};
                #pragma unroll
                for (int u = 0; u < 4; u++) {
                    float p = __fmul_rn(sz[q * 4 + u], el[u]);
                    float y = __fadd_rn(p, -c);
                    float t = __fadd_rn(s, y);
                    c = __fadd_rn(__fadd_rn(t, -s), -y);
                    s = t;
                }
            }
            float dot = __fadd_rn(s, c);
            float dd  = __fadd_rn(__fadd_rn(z2, g_e2[j]), -2.f * dot);
            if (dd < bestd || (dd == bestd && j < besti)) { bestd = dd; besti = j; }
        }

        sd[threadIdx.x] = bestd;
        si[threadIdx.x] = besti;
        __syncthreads();
        #pragma unroll
        for (int st = REFINE_THREADS / 2; st > 0; st >>= 1) {
            if (threadIdx.x < st) {
                float od = sd[threadIdx.x + st];
                int   oi = si[threadIdx.x + st];
                if (od < sd[threadIdx.x] ||
                    (od == sd[threadIdx.x] && oi < si[threadIdx.x])) {
                    sd[threadIdx.x] = od;
                    si[threadIdx.x] = oi;
                }
            }
            __syncthreads();
        }
        if (threadIdx.x == 0) {
            g_idx[row]     = si[0];
            idx_out_f[row] = (float)si[0];
        }
        __syncthreads();
    }
}

// ---------------------------------------------------------------------------
// Kernel 3: zq gather, 4 threads/row. out = z + (e - z), fp32, matching the
// reference straight-through expression. zq_out 4B-aligned -> scalar stores.
// ---------------------------------------------------------------------------
__global__ __launch_bounds__(K3_THREADS)
void gather_kernel(const float* __restrict__ z,
                   const float* __restrict__ emb,
                   float* __restrict__ zq_out) {
    int gt   = blockIdx.x * K3_THREADS + threadIdx.x;
    int row  = gt >> 2;
    int part = gt & 3;
    int j    = g_idx[row];

    const float4* ef = (const float4*)(emb + (size_t)j * D + part * 16);
    const float4* zf = (const float4*)(z + (size_t)row * D + part * 16);
    float*        o  = zq_out + (size_t)row * D + part * 16;

    #pragma unroll
    for (int q = 0; q < 4; q++) {
        float4 e  = ef[q];
        float4 zv = zf[q];
        o[q * 4 + 0] = __fadd_rn(zv.x, __fadd_rn(e.x, -zv.x));
        o[q * 4 + 1] = __fadd_rn(zv.y, __fadd_rn(e.y, -zv.y));
        o[q * 4 + 2] = __fadd_rn(zv.z, __fadd_rn(e.z, -zv.z));
        o[q * 4 + 3] = __fadd_rn(zv.w, __fadd_rn(e.w, -zv.w));
    }
}

// ---------------------------------------------------------------------------
// Kernel 4: final loss reduction over 256 partials.
// loss = 1.25 * sum / (N*D)
// ---------------------------------------------------------------------------
__global__ void final_kernel(float* __restrict__ out) {
    __shared__ float red[K2_BLOCKS];
    red[threadIdx.x] = g_partial[threadIdx.x];
    __syncthreads();
    #pragma unroll
    for (int st = K2_BLOCKS / 2; st > 0; st >>= 1) {
        if (threadIdx.x < st) red[threadIdx.x] += red[threadIdx.x + st];
        __syncthreads();
    }
    if (threadIdx.x == 0)
        out[0] = 1.25f * red[0] / (float)(N_ROWS * D);
}

// ---------------------------------------------------------------------------
// Launch: out layout = [loss(1) | z_q(N_ROWS*D) | indices(N_ROWS)] fp32
// ---------------------------------------------------------------------------
extern "C" void kernel_launch(void* const* d_in, const int* in_sizes, int n_in,
                              void* d_out, int out_size) {
    const float* z   = (const float*)d_in[0];
    const float* emb = (const float*)d_in[1];
    float* out     = (float*)d_out;
    float* zq_out  = out + 1;
    float* idx_out = out + 1 + (size_t)N_ROWS * D;

    e2_kernel<<<(NE + 255) / 256, 256>>>(emb);
    argmin_kernel<<<K2_BLOCKS, K2_THREADS>>>(z, emb, idx_out);
    refine_kernel<<<REFINE_BLOCKS, REFINE_THREADS>>>(z, emb, idx_out);
    gather_kernel<<<K3_BLOCKS, K3_THREADS>>>(z, emb, zq_out);
    final_kernel<<<1, K2_BLOCKS>>>(out);
}

// round 8
// speedup vs baseline: 1.4615x; 1.3338x over previous
#include <cuda_runtime.h>
#include <cuda_bf16.h>
#include <cstdint>

#define N_ROWS 65536
#define D      64
#define NE     1024
#define M_TILE 128                     // rows per CTA (8 warps x m16)
#define NC     64                      // codes per chunk
#define NUM_CHUNKS (NE / NC)           // 16
#define GRID_MAIN (N_ROWS / M_TILE)    // 512
#define GAP_THRESH 2e-4f
#define REFINE_BLOCKS 256
#define REFINE_THREADS 128
#define K3_THREADS 256
#define K3_BLOCKS  (N_ROWS * 4 / K3_THREADS)   // 1024
#define BSTRIDE 72                     // padded smem row stride (elems) = 144 B

// ---------------- scratch (no allocations allowed) ----------------
__device__ float g_e2[NE];
__device__ __align__(16) __nv_bfloat16 g_ehi[NE * D];
__device__ __align__(16) __nv_bfloat16 g_elo[NE * D];
__device__ int   g_idx[N_ROWS];
__device__ float g_partial[GRID_MAIN];
__device__ int   g_flag_cnt;
__device__ int   g_flag_rows[N_ROWS];

// ---------------- helpers ----------------
__device__ __forceinline__ uint32_t smem_u32(const void* p) {
    uint32_t a;
    asm("{ .reg .u64 t; cvta.to.shared.u64 t, %1; cvt.u32.u64 %0, t; }"
        : "=r"(a) : "l"(p));
    return a;
}
__device__ __forceinline__ uint32_t bfpair(__nv_bfloat16 a, __nv_bfloat16 b) {
    __nv_bfloat162 t(a, b);            // a = low 16 bits
    return *reinterpret_cast<uint32_t*>(&t);
}
__device__ __forceinline__ void mma_bf16(float& d0, float& d1, float& d2, float& d3,
                                         uint32_t a0, uint32_t a1, uint32_t a2, uint32_t a3,
                                         uint32_t b0, uint32_t b1) {
    asm volatile(
        "mma.sync.aligned.m16n8k16.row.col.f32.bf16.bf16.f32 "
        "{%0,%1,%2,%3}, {%4,%5,%6,%7}, {%8,%9}, {%0,%1,%2,%3};"
        : "+f"(d0), "+f"(d1), "+f"(d2), "+f"(d3)
        : "r"(a0), "r"(a1), "r"(a2), "r"(a3), "r"(b0), "r"(b1));
}
__device__ __forceinline__ void ldsm_x2(uint32_t& r0, uint32_t& r1, uint32_t addr) {
    asm volatile("ldmatrix.sync.aligned.m8n8.x2.shared.b16 {%0,%1}, [%2];"
                 : "=r"(r0), "=r"(r1) : "r"(addr));
}
// merge two (best, best2, idx) candidate sets (union top-2), min-index tiebreak
__device__ __forceinline__ void merge_top2(float& b, float& b2, int& i, int off) {
    float ob  = __shfl_xor_sync(0xffffffffu, b,  off);
    float ob2 = __shfl_xor_sync(0xffffffffu, b2, off);
    int   oi  = __shfl_xor_sync(0xffffffffu, i,  off);
    int   ni  = (ob < b || (ob == b && oi < i)) ? oi : i;
    float nb2 = fminf(fmaxf(b, ob), fminf(b2, ob2));
    b  = fminf(b, ob);
    b2 = nb2;
    i  = ni;
}

// ---------------------------------------------------------------------------
// Kernel 1: per-code prep: e2 (fp32), bf16 hi/lo split. + reset flag counter.
// ---------------------------------------------------------------------------
__global__ void prep_kernel(const float* __restrict__ emb) {
    int j = blockIdx.x * blockDim.x + threadIdx.x;
    if (j == 0) g_flag_cnt = 0;
    if (j < NE) {
        const float* e = emb + (size_t)j * D;
        float s = 0.f;
        #pragma unroll
        for (int k = 0; k < D; k++) {
            float v = e[k];
            s += v * v;
            __nv_bfloat16 h = __float2bfloat16_rn(v);
            g_ehi[j * D + k] = h;
            g_elo[j * D + k] = __float2bfloat16_rn(v - __bfloat162float(h));
        }
        g_e2[j] = s;
    }
}

// ---------------------------------------------------------------------------
// Kernel 2: HMMA argmin via mma.sync m16n8k16 bf16 (portable PTX; tcgen05 is
// unavailable on the harness's compute_103 target).
// CTA = 8 warps, each owns an m16 row tile. A (z hi/lo) fragments built
// directly from gmem, held in regs for the whole kernel. B (codes, TN layout)
// staged per 64-code chunk in padded smem; ldmatrix.x2 -> fragments.
// dot = Zhi*Bhi + Zhi*Blo + Zlo*Bhi (fp32 accum); |d err| <~1e-5 << GAP_THRESH.
// Per n-tile epilogue tracks best/second-best; near-ties -> refine list.
// ---------------------------------------------------------------------------
__global__ __launch_bounds__(256, 2)
void argmin_tc_kernel(const float* __restrict__ z,
                      float* __restrict__ idx_out_f) {
    __shared__ __align__(16) __nv_bfloat16 sBhi[NC * BSTRIDE];
    __shared__ __align__(16) __nv_bfloat16 sBlo[NC * BSTRIDE];
    __shared__ float sE2[NC];
    __shared__ float sLoss[8];

    int tid  = threadIdx.x;
    int wid  = tid >> 5;
    int lane = tid & 31;
    int grp  = lane >> 2;         // 0..7  (row within tile)
    int c    = lane & 3;          // 0..3  (pair column)

    // ---- A fragments (hi/lo) straight from gmem; z2 per row via group shfl ----
    int rbase = blockIdx.x * M_TILE + wid * 16;
    int r0 = rbase + grp;         // rows grp and grp+8 of this warp's m16 tile
    uint32_t ahi[16], alo[16];
    float z2_0 = 0.f, z2_1 = 0.f;
    {
        const float* zr0 = z + (size_t)r0 * D;
        const float* zr1 = zr0 + 8 * D;
        #pragma unroll
        for (int t = 0; t < 4; t++) {
            float2 p0 = *(const float2*)(zr0 + 16 * t + 2 * c);
            float2 p1 = *(const float2*)(zr1 + 16 * t + 2 * c);
            float2 p2 = *(const float2*)(zr0 + 16 * t + 8 + 2 * c);
            float2 p3 = *(const float2*)(zr1 + 16 * t + 8 + 2 * c);
            z2_0 += p0.x * p0.x + p0.y * p0.y + p2.x * p2.x + p2.y * p2.y;
            z2_1 += p1.x * p1.x + p1.y * p1.y + p3.x * p3.x + p3.y * p3.y;
            float2 ps[4] = {p0, p1, p2, p3};
            #pragma unroll
            for (int u = 0; u < 4; u++) {
                __nv_bfloat16 hx = __float2bfloat16_rn(ps[u].x);
                __nv_bfloat16 hy = __float2bfloat16_rn(ps[u].y);
                ahi[t * 4 + u] = bfpair(hx, hy);
                alo[t * 4 + u] = bfpair(
                    __float2bfloat16_rn(ps[u].x - __bfloat162float(hx)),
                    __float2bfloat16_rn(ps[u].y - __bfloat162float(hy)));
            }
        }
        // full-row z2: 4 lanes of the group cover disjoint k's
        z2_0 += __shfl_xor_sync(0xffffffffu, z2_0, 1);
        z2_0 += __shfl_xor_sync(0xffffffffu, z2_0, 2);
        z2_1 += __shfl_xor_sync(0xffffffffu, z2_1, 1);
        z2_1 += __shfl_xor_sync(0xffffffffu, z2_1, 2);
    }

    float b0 = 3.402823466e38f, b20 = 3.402823466e38f;  // row r0
    float b1 = 3.402823466e38f, b21 = 3.402823466e38f;  // row r0+8
    int   i0 = 0, i1 = 0;

    uint32_t sbhi = smem_u32(sBhi);
    uint32_t sblo = smem_u32(sBlo);
    // ldmatrix per-lane row address component (lanes 16-31 mirror 0-15)
    int ll = lane & 15;
    uint32_t lrow = (uint32_t)(ll & 7) * (BSTRIDE * 2) + ((uint32_t)(ll >> 3)) * 16;

    for (int ch = 0; ch < NUM_CHUNKS; ch++) {
        int cbase = ch * NC;
        __syncthreads();
        // ---- stage B chunk (hi/lo) + e2 ----
        {
            int row = tid >> 2, q = tid & 3;     // 64 rows x 4 quarters
            const uint4* sh = (const uint4*)(g_ehi + (size_t)(cbase + row) * D + q * 16);
            const uint4* sl = (const uint4*)(g_elo + (size_t)(cbase + row) * D + q * 16);
            uint4* dh = (uint4*)(sBhi + row * BSTRIDE + q * 16);
            uint4* dl = (uint4*)(sBlo + row * BSTRIDE + q * 16);
            dh[0] = sh[0]; dh[1] = sh[1];
            dl[0] = sl[0]; dl[1] = sl[1];
            if (tid < NC) sE2[tid] = g_e2[cbase + tid];
        }
        __syncthreads();

        #pragma unroll 1
        for (int nt = 0; nt < NC / 8; nt++) {
            float d0 = 0.f, d1 = 0.f, d2 = 0.f, d3 = 0.f;
            uint32_t nbase = (uint32_t)(nt * 8) * (BSTRIDE * 2) + lrow;
            #pragma unroll
            for (int t = 0; t < 4; t++) {
                uint32_t bh0, bh1, bl0, bl1;
                ldsm_x2(bh0, bh1, sbhi + nbase + t * 32);
                ldsm_x2(bl0, bl1, sblo + nbase + t * 32);
                mma_bf16(d0, d1, d2, d3, ahi[t*4+0], ahi[t*4+1], ahi[t*4+2], ahi[t*4+3], bh0, bh1);
                mma_bf16(d0, d1, d2, d3, ahi[t*4+0], ahi[t*4+1], ahi[t*4+2], ahi[t*4+3], bl0, bl1);
                mma_bf16(d0, d1, d2, d3, alo[t*4+0], alo[t*4+1], alo[t*4+2], alo[t*4+3], bh0, bh1);
            }
            // ---- epilogue for this n-tile ----
            int ca = cbase + nt * 8 + 2 * c;
            float ea = sE2[nt * 8 + 2 * c];
            float eb = sE2[nt * 8 + 2 * c + 1];
            float dd0 = (z2_0 + ea) - 2.f * d0;
            float dd1 = (z2_0 + eb) - 2.f * d1;
            float dd2 = (z2_1 + ea) - 2.f * d2;
            float dd3 = (z2_1 + eb) - 2.f * d3;
            if (dd0 < b0) { b20 = b0; b0 = dd0; i0 = ca; }
            else if (dd0 < b20) b20 = dd0;
            if (dd1 < b0) { b20 = b0; b0 = dd1; i0 = ca + 1; }
            else if (dd1 < b20) b20 = dd1;
            if (dd2 < b1) { b21 = b1; b1 = dd2; i1 = ca; }
            else if (dd2 < b21) b21 = dd2;
            if (dd3 < b1) { b21 = b1; b1 = dd3; i1 = ca + 1; }
            else if (dd3 < b21) b21 = dd3;
        }
    }

    // ---- merge across the 4 lanes of each row group ----
    merge_top2(b0, b20, i0, 1); merge_top2(b0, b20, i0, 2);
    merge_top2(b1, b21, i1, 1); merge_top2(b1, b21, i1, 2);

    if (c == 0) {
        int r1 = r0 + 8;
        g_idx[r0] = i0;            g_idx[r1] = i1;
        idx_out_f[r0] = (float)i0; idx_out_f[r1] = (float)i1;
        if (b20 - b0 < GAP_THRESH) { int s = atomicAdd(&g_flag_cnt, 1); g_flag_rows[s] = r0; }
        if (b21 - b1 < GAP_THRESH) { int s = atomicAdd(&g_flag_cnt, 1); g_flag_rows[s] = r1; }
    }

    // ---- loss partial: sum of bestd over the CTA's 128 rows ----
    float v = (c == 0) ? (b0 + b1) : 0.f;
    #pragma unroll
    for (int o = 16; o > 0; o >>= 1) v += __shfl_down_sync(0xffffffffu, v, o);
    if (lane == 0) sLoss[wid] = v;
    __syncthreads();
    if (tid == 0) {
        float s = 0.f;
        #pragma unroll
        for (int w = 0; w < 8; w++) s += sLoss[w];
        g_partial[blockIdx.x] = s;
    }
}

// ---------------------------------------------------------------------------
// Kernel 2b: refine flagged rows with Kahan-compensated exact fp32 dots;
// rewrites g_idx + idx_out only (gather re-reads g_idx afterwards).
// ---------------------------------------------------------------------------
__global__ __launch_bounds__(REFINE_THREADS)
void refine_kernel(const float* __restrict__ z,
                   const float* __restrict__ emb,
                   float* __restrict__ idx_out_f) {
    __shared__ float sz[D];
    __shared__ float sd[REFINE_THREADS];
    __shared__ int   si[REFINE_THREADS];

    int cnt = g_flag_cnt;
    for (int w = blockIdx.x; w < cnt; w += gridDim.x) {
        int row = g_flag_rows[w];

        __syncthreads();
        if (threadIdx.x < D) sz[threadIdx.x] = z[(size_t)row * D + threadIdx.x];
        __syncthreads();

        float z2 = 0.f;
        #pragma unroll
        for (int k = 0; k < D; k++) z2 += sz[k] * sz[k];

        float bestd = 3.402823466e38f;
        int   besti = NE;

        for (int j = threadIdx.x; j < NE; j += REFINE_THREADS) {
            const float4* e = (const float4*)(emb + (size_t)j * D);
            float4 ev[16];
            #pragma unroll
            for (int q = 0; q < 16; q++) ev[q] = e[q];

            float s = 0.f, cc = 0.f;
            #pragma unroll
            for (int q = 0; q < 16; q++) {
                float el[4] = {ev[q].x, ev[q].y, ev[q].z, ev[q].w};
                #pragma unroll
                for (int u = 0; u < 4; u++) {
                    float p = __fmul_rn(sz[q * 4 + u], el[u]);
                    float y = __fadd_rn(p, -cc);
                    float t = __fadd_rn(s, y);
                    cc = __fadd_rn(__fadd_rn(t, -s), -y);
                    s = t;
                }
            }
            float dot = __fadd_rn(s, cc);
            float dd  = __fadd_rn(__fadd_rn(z2, g_e2[j]), -2.f * dot);
            if (dd < bestd || (dd == bestd && j < besti)) { bestd = dd; besti = j; }
        }

        sd[threadIdx.x] = bestd;
        si[threadIdx.x] = besti;
        __syncthreads();
        #pragma unroll
        for (int st = REFINE_THREADS / 2; st > 0; st >>= 1) {
            if (threadIdx.x < st) {
                float od = sd[threadIdx.x + st];
                int   oi = si[threadIdx.x + st];
                if (od < sd[threadIdx.x] ||
                    (od == sd[threadIdx.x] && oi < si[threadIdx.x])) {
                    sd[threadIdx.x] = od;
                    si[threadIdx.x] = oi;
                }
            }
            __syncthreads();
        }
        if (threadIdx.x == 0) {
            g_idx[row]     = si[0];
            idx_out_f[row] = (float)si[0];
        }
        __syncthreads();
    }
}

// ---------------------------------------------------------------------------
// Kernel 3: zq gather, 4 threads/row. out = z + (e - z) (straight-through).
// zq_out only 4B-aligned -> scalar stores.
// ---------------------------------------------------------------------------
__global__ __launch_bounds__(K3_THREADS)
void gather_kernel(const float* __restrict__ z,
                   const float* __restrict__ emb,
                   float* __restrict__ zq_out) {
    int gt   = blockIdx.x * K3_THREADS + threadIdx.x;
    int row  = gt >> 2;
    int part = gt & 3;
    int j    = g_idx[row];

    const float4* ef = (const float4*)(emb + (size_t)j * D + part * 16);
    const float4* zf = (const float4*)(z + (size_t)row * D + part * 16);
    float*        o  = zq_out + (size_t)row * D + part * 16;

    #pragma unroll
    for (int q = 0; q < 4; q++) {
        float4 e  = ef[q];
        float4 zv = zf[q];
        o[q * 4 + 0] = __fadd_rn(zv.x, __fadd_rn(e.x, -zv.x));
        o[q * 4 + 1] = __fadd_rn(zv.y, __fadd_rn(e.y, -zv.y));
        o[q * 4 + 2] = __fadd_rn(zv.z, __fadd_rn(e.z, -zv.z));
        o[q * 4 + 3] = __fadd_rn(zv.w, __fadd_rn(e.w, -zv.w));
    }
}

// ---------------------------------------------------------------------------
// Kernel 4: final loss reduction over 512 partials.
// loss = 1.25 * sum / (N*D)
// ---------------------------------------------------------------------------
__global__ void final_kernel(float* __restrict__ out) {
    __shared__ float red[256];
    red[threadIdx.x] = g_partial[threadIdx.x] + g_partial[threadIdx.x + 256];
    __syncthreads();
    #pragma unroll
    for (int st = 128; st > 0; st >>= 1) {
        if (threadIdx.x < st) red[threadIdx.x] += red[threadIdx.x + st];
        __syncthreads();
    }
    if (threadIdx.x == 0)
        out[0] = 1.25f * red[0] / (float)(N_ROWS * D);
}

// ---------------------------------------------------------------------------
// Launch: out layout = [loss(1) | z_q(N_ROWS*D) | indices(N_ROWS)] fp32
// ---------------------------------------------------------------------------
extern "C" void kernel_launch(void* const* d_in, const int* in_sizes, int n_in,
                              void* d_out, int out_size) {
    const float* z   = (const float*)d_in[0];
    const float* emb = (const float*)d_in[1];
    float* out     = (float*)d_out;
    float* zq_out  = out + 1;
    float* idx_out = out + 1 + (size_t)N_ROWS * D;

    prep_kernel<<<4, 256>>>(emb);
    argmin_tc_kernel<<<GRID_MAIN, 256>>>(z, idx_out);
    refine_kernel<<<REFINE_BLOCKS, REFINE_THREADS>>>(z, emb, idx_out);
    gather_kernel<<<K3_BLOCKS, K3_THREADS>>>(z, emb, zq_out);
    final_kernel<<<1, 256>>>(out);
}